// round 16
// baseline (speedup 1.0000x reference)
#include <cuda_runtime.h>
#include <cuda_fp16.h>
#include <cstdint>

#define TQ    16384
#define DIN   1024
#define DOUT  1024
#define NE    8
#define BM    128
#define BN    128
#define BK    64
#define NKITER (DIN / BK)          // 16
#define MAXTILES (TQ / BM + NE)    // 136
#define NSTAGE 3

// smem tiles in half: row = 64 halves + 8 pad = 72 halves = 144 B
#define TSTRIDE_H 72
#define TILE_HALVES (BM * TSTRIDE_H)                 // 9216
#define TILE_BYTES  (TILE_HALVES * 2)                // 18432
#define STAGE_BYTES (2 * TILE_BYTES)                 // A + B = 36864
#define SMEM_BYTES  (NSTAGE * STAGE_BYTES)           // 110592

// ---------------- scratch (device globals; no allocations) ----------------
__device__ int g_offsets[NE + 1];
__device__ int g_cursor[NE];
__device__ int g_perm[TQ];
__device__ int g_tile_expert[MAXTILES];
__device__ int g_tile_start[MAXTILES];
__device__ __half g_xh[(size_t)TQ * DIN];             // x in fp16, PERMUTED (packed by expert)
__device__ __half g_Wth[(size_t)NE * DOUT * DIN];     // W^T in fp16: [e][out][in]

// ---------------- fused init+count+scan (one block) ----------------
__global__ void k_bin(const int* __restrict__ idxs) {
    __shared__ int wh[32][NE];          // per-warp histograms
    const int tid = threadIdx.x;        // 1024 threads
    const int warp = tid >> 5;
    if ((tid & 31) < NE) wh[warp][tid & 31] = 0;
    __syncthreads();
    const int4* iv = reinterpret_cast<const int4*>(idxs);
#pragma unroll
    for (int i = 0; i < 4; i++) {
        int4 v = iv[i * 1024 + tid];
        atomicAdd(&wh[warp][v.x], 1);
        atomicAdd(&wh[warp][v.y], 1);
        atomicAdd(&wh[warp][v.z], 1);
        atomicAdd(&wh[warp][v.w], 1);
    }
    __syncthreads();
    if (tid == 0) {
        int off = 0;
        for (int e = 0; e < NE; e++) {
            int c = 0;
            for (int w = 0; w < 32; w++) c += wh[w][e];
            g_offsets[e] = off;
            g_cursor[e]  = off;
            off += c;
        }
        g_offsets[NE] = off;
        int nt = 0;
        for (int e = 0; e < NE; e++)
            for (int s = g_offsets[e]; s < g_offsets[e + 1]; s += BM) {
                g_tile_expert[nt] = e;
                g_tile_start[nt]  = s;
                nt++;
            }
        for (; nt < MAXTILES; nt++) g_tile_expert[nt] = -1;
    }
}

// ---------------- fused scatter + gather-pack-convert ----------------
// Block of 128 threads owns 128 tokens: computes perm slots via block-aggregated
// atomics, writes g_perm, then cooperatively converts those rows into g_xh.
__global__ __launch_bounds__(128)
void k_pack(const int* __restrict__ idxs, const float* __restrict__ x) {
    __shared__ int lh[NE];
    __shared__ int base[NE];
    __shared__ int s_p[128];
    __shared__ int s_t[128];
    const int tid = threadIdx.x;
    if (tid < NE) lh[tid] = 0;
    __syncthreads();
    const int t = blockIdx.x * 128 + tid;
    const int e = idxs[t];
    const int r = atomicAdd(&lh[e], 1);
    __syncthreads();
    if (tid < NE)
        base[tid] = atomicAdd(&g_cursor[tid], lh[tid]);
    __syncthreads();
    const int p = base[e] + r;
    g_perm[p] = t;
    s_p[tid] = p;
    s_t[tid] = t;
    __syncthreads();

    // copy+convert 128 rows; each row: 128 thr x 8 floats (2x float4 -> 1x half-float4)
    for (int row = 0; row < 128; row++) {
        const float* src = x + (size_t)s_t[row] * DIN + tid * 8;
        float4 v0 = *reinterpret_cast<const float4*>(src);
        float4 v1 = *reinterpret_cast<const float4*>(src + 4);
        __half2 h[4];
        h[0] = __float22half2_rn(make_float2(v0.x, v0.y));
        h[1] = __float22half2_rn(make_float2(v0.z, v0.w));
        h[2] = __float22half2_rn(make_float2(v1.x, v1.y));
        h[3] = __float22half2_rn(make_float2(v1.z, v1.w));
        *reinterpret_cast<uint4*>(g_xh + (size_t)s_p[row] * DIN + tid * 8) =
            *reinterpret_cast<uint4*>(h);
    }
}

// ---------------- W transpose + convert: g_Wth[e][o][k] = half(W[e][k][o]) --------
__global__ void k_wconv(const float* __restrict__ W) {
    __shared__ float t[32][33];
    const int tid = threadIdx.x;
    int bid = blockIdx.x;
    int e = bid >> 10;
    int rem = bid & 1023;
    int k0 = (rem >> 5) * 32, o0 = (rem & 31) * 32;
    const float* Ws = W + (size_t)e * DIN * DOUT;
    __half* Wd = g_Wth + (size_t)e * DOUT * DIN;
    int tx = tid & 31, ty = tid >> 5;   // 32 x 8
#pragma unroll
    for (int j = 0; j < 4; j++)
        t[ty + j * 8][tx] = Ws[(size_t)(k0 + ty + j * 8) * DOUT + o0 + tx];
    __syncthreads();
#pragma unroll
    for (int j = 0; j < 4; j++)
        Wd[(size_t)(o0 + ty + j * 8) * DIN + k0 + tx] = __float2half(t[tx][ty + j * 8]);
}

// ---------------- GEMM helpers ----------------
__device__ __forceinline__ void cp_async16(uint32_t dst, const void* src) {
    asm volatile("cp.async.cg.shared.global [%0], [%1], 16;\n" :: "r"(dst), "l"(src));
}

__device__ __forceinline__ void ldsm_x4(uint32_t r[4], uint32_t addr) {
    asm volatile("ldmatrix.sync.aligned.m8n8.x4.shared.b16 {%0,%1,%2,%3}, [%4];"
                 : "=r"(r[0]), "=r"(r[1]), "=r"(r[2]), "=r"(r[3]) : "r"(addr));
}

__device__ __forceinline__ void mma_f16(float d[4], const uint32_t a[4], const uint32_t b[2]) {
    asm volatile(
        "mma.sync.aligned.m16n8k16.row.col.f32.f16.f16.f32 "
        "{%0,%1,%2,%3}, {%4,%5,%6,%7}, {%8,%9}, {%0,%1,%2,%3};\n"
        : "+f"(d[0]), "+f"(d[1]), "+f"(d[2]), "+f"(d[3])
        : "r"(a[0]), "r"(a[1]), "r"(a[2]), "r"(a[3]),
          "r"(b[0]), "r"(b[1]));
}

__device__ __forceinline__ uint32_t smem_u32(const void* p) {
    return (uint32_t)__cvta_generic_to_shared(p);
}

// ---------------- GEMM (round-9 config: 8 warps of 64x32, 256 thr, 2 CTAs/SM) -------
// grid=(DOUT/BN, MAXTILES): n fastest so CTAs sharing a row-tile hit L2 on packed A rows.
__global__ __launch_bounds__(256, 2)
void k_gemm(const float* __restrict__ bias, float* __restrict__ y)
{
    const int tile = blockIdx.y;
    const int e = g_tile_expert[tile];
    if (e < 0) return;
    const int row0 = g_tile_start[tile];
    const int row_end = g_offsets[e + 1];
    const int n0 = blockIdx.x * BN;

    extern __shared__ __half smem[];
    const uint32_t sbase = smem_u32(smem);

    const int tid  = threadIdx.x;
    const int lane = tid & 31;
    const int warp = tid >> 5;
    const int warpM = warp >> 2;     // 0..1  (64-row slab)
    const int warpN = warp & 3;      // 0..3  (32-col slab)

    const int q  = lane >> 3;        // ldmatrix matrix id
    const int rl = lane & 7;         // row within 8x8 matrix

    // A: matrices [m0-7,k0-7][m8-15,k0-7][m0-7,k8-15][m8-15,k8-15]
    uint32_t aoff[4];
#pragma unroll
    for (int mi = 0; mi < 4; mi++) {
        int row = warpM * 64 + mi * 16 + (q & 1) * 8 + rl;
        aoff[mi] = (uint32_t)(row * TSTRIDE_H + (q >> 1) * 8) * 2;
    }
    // B (n-major rows of W^T): matrices [n0-7,k0-7][n0-7,k8-15][n8-15,k0-7][n8-15,k8-15]
    uint32_t boff[2];
#pragma unroll
    for (int j = 0; j < 2; j++) {
        int row = warpN * 32 + 16 * j + (q >> 1) * 8 + rl;
        boff[j] = (uint32_t)(row * TSTRIDE_H + (q & 1) * 8) * 2 + TILE_BYTES;
    }

    const __half* wt = g_Wth + (size_t)(e * DOUT + n0) * DIN;
    const int cc = tid & 7;           // 16B chunk col (8 halves each)

    int arow[4];
#pragma unroll
    for (int i = 0; i < 4; i++) {
        int r = (i * 256 + tid) >> 3;
        int gr = row0 + r;
        arow[i] = (gr < TQ) ? gr : (TQ - 1);
    }

    auto prefetch = [&](int kt) {
        const uint32_t st = sbase + (kt % NSTAGE) * STAGE_BYTES;
        const int k0 = kt * BK;
#pragma unroll
        for (int i = 0; i < 4; i++) {
            int r = (i * 256 + tid) >> 3;
            cp_async16(st + (uint32_t)(r * TSTRIDE_H + cc * 8) * 2,
                       g_xh + (size_t)arow[i] * DIN + k0 + cc * 8);
        }
#pragma unroll
        for (int i = 0; i < 4; i++) {
            int n = (i * 256 + tid) >> 3;
            cp_async16(st + TILE_BYTES + (uint32_t)(n * TSTRIDE_H + cc * 8) * 2,
                       wt + (size_t)n * DIN + k0 + cc * 8);
        }
        asm volatile("cp.async.commit_group;\n" ::);
    };

    float acc[4][4][4] = {};   // [mi][nj][frag]

    prefetch(0);
    prefetch(1);

    for (int kt = 0; kt < NKITER; kt++) {
        if (kt < NKITER - 1) {
            asm volatile("cp.async.wait_group 1;\n" ::);
        } else {
            asm volatile("cp.async.wait_group 0;\n" ::);
        }
        __syncthreads();
        if (kt + 2 < NKITER) prefetch(kt + 2);

        const uint32_t st = sbase + (kt % NSTAGE) * STAGE_BYTES;

#pragma unroll
        for (int ks = 0; ks < BK; ks += 16) {
            uint32_t af[4][4], bp[2][4];
#pragma unroll
            for (int mi = 0; mi < 4; mi++)
                ldsm_x4(af[mi], st + aoff[mi] + ks * 2);
#pragma unroll
            for (int j = 0; j < 2; j++)
                ldsm_x4(bp[j], st + boff[j] + ks * 2);
            // bp[j]: r0,r1 = B frag for n-octet 2j; r2,r3 = n-octet 2j+1
#pragma unroll
            for (int mi = 0; mi < 4; mi++)
#pragma unroll
                for (int nj = 0; nj < 4; nj++)
                    mma_f16(acc[mi][nj], af[mi], &bp[nj >> 1][(nj & 1) * 2]);
        }
    }

    // Epilogue: bias + relu + scatter store (perm only here)
    const int grp = lane >> 2;
    const int c4  = lane & 3;
#pragma unroll
    for (int mi = 0; mi < 4; mi++) {
#pragma unroll
        for (int h = 0; h < 2; h++) {
            int mrow = warpM * 64 + mi * 16 + grp + h * 8;
            int gr = row0 + mrow;
            if (gr >= row_end) continue;
            int tok = g_perm[gr];
#pragma unroll
            for (int nj = 0; nj < 4; nj++) {
                int n = n0 + warpN * 32 + nj * 8 + 2 * c4;
                float v0 = acc[mi][nj][h * 2 + 0] + __ldg(&bias[e * DOUT + n]);
                float v1 = acc[mi][nj][h * 2 + 1] + __ldg(&bias[e * DOUT + n + 1]);
                float2 out;
                out.x = fmaxf(v0, 0.0f);
                out.y = fmaxf(v1, 0.0f);
                *reinterpret_cast<float2*>(y + (size_t)tok * DOUT + n) = out;
            }
        }
    }
}

// ---------------- launch ----------------
extern "C" void kernel_launch(void* const* d_in, const int* in_sizes, int n_in,
                              void* d_out, int out_size) {
    const float* x    = (const float*)d_in[0];
    const int*   idxs = (const int*)  d_in[1];
    const float* W    = (const float*)d_in[2];
    const float* b    = (const float*)d_in[3];
    float* y = (float*)d_out;

    cudaFuncSetAttribute(k_gemm, cudaFuncAttributeMaxDynamicSharedMemorySize, SMEM_BYTES);

    k_bin<<<1, 1024>>>(idxs);
    k_pack<<<TQ / 128, 128>>>(idxs, x);
    k_wconv<<<NE * (DIN / 32) * (DOUT / 32), 256>>>(W);

    dim3 grid(DOUT / BN, MAXTILES);
    k_gemm<<<grid, 256, SMEM_BYTES>>>(b, y);
}

// round 17
// speedup vs baseline: 1.1331x; 1.1331x over previous
#include <cuda_runtime.h>
#include <cuda_fp16.h>
#include <cstdint>

#define TQ    16384
#define DIN   1024
#define DOUT  1024
#define NE    8
#define BM    128
#define BN    128
#define BK    64
#define NKITER (DIN / BK)          // 16
#define MAXTILES (TQ / BM + NE)    // 136
#define NSTAGE 3

// smem tiles in half: row = 64 halves + 8 pad = 72 halves = 144 B
#define TSTRIDE_H 72
#define TILE_HALVES (BM * TSTRIDE_H)                 // 9216
#define TILE_BYTES  (TILE_HALVES * 2)                // 18432
#define STAGE_BYTES (2 * TILE_BYTES)                 // A + B = 36864
#define SMEM_BYTES  (NSTAGE * STAGE_BYTES)           // 110592

// ---------------- scratch (device globals; no allocations) ----------------
__device__ int g_offsets[NE + 1];
__device__ int g_perm[TQ];
__device__ int g_tile_expert[MAXTILES];
__device__ int g_tile_start[MAXTILES];
__device__ __half g_xh[(size_t)TQ * DIN];             // x in fp16, PERMUTED (packed by expert)
__device__ __half g_Wth[(size_t)NE * DOUT * DIN];     // W^T in fp16: [e][out][in]

// ---------------- fused init+count+scan+scatter (one block, 1024 thr) ----------------
// Each thread keeps its 16 expert ids in registers across the two phases.
__global__ void k_binscatter(const int* __restrict__ idxs) {
    __shared__ int wh[32][NE];          // per-warp histograms
    __shared__ int cur[NE];             // scatter cursors
    const int tid = threadIdx.x;
    const int warp = tid >> 5;
    if ((tid & 31) < NE) wh[warp][tid & 31] = 0;
    __syncthreads();
    const int4* iv = reinterpret_cast<const int4*>(idxs);
    int4 v[4];
#pragma unroll
    for (int i = 0; i < 4; i++) {
        v[i] = iv[i * 1024 + tid];
        atomicAdd(&wh[warp][v[i].x], 1);
        atomicAdd(&wh[warp][v[i].y], 1);
        atomicAdd(&wh[warp][v[i].z], 1);
        atomicAdd(&wh[warp][v[i].w], 1);
    }
    __syncthreads();
    if (tid == 0) {
        int off = 0;
        for (int e = 0; e < NE; e++) {
            int c = 0;
            for (int w = 0; w < 32; w++) c += wh[w][e];
            g_offsets[e] = off;
            cur[e] = off;
            off += c;
        }
        g_offsets[NE] = off;
        int nt = 0;
        for (int e = 0; e < NE; e++)
            for (int s = g_offsets[e]; s < g_offsets[e + 1]; s += BM) {
                g_tile_expert[nt] = e;
                g_tile_start[nt]  = s;
                nt++;
            }
        for (; nt < MAXTILES; nt++) g_tile_expert[nt] = -1;
    }
    __syncthreads();
    // scatter from registers (order within an expert bin is irrelevant)
#pragma unroll
    for (int i = 0; i < 4; i++) {
        int t0 = (i * 1024 + tid) * 4;
        int r;
        r = atomicAdd(&cur[v[i].x], 1); g_perm[r] = t0;
        r = atomicAdd(&cur[v[i].y], 1); g_perm[r] = t0 + 1;
        r = atomicAdd(&cur[v[i].z], 1); g_perm[r] = t0 + 2;
        r = atomicAdd(&cur[v[i].w], 1); g_perm[r] = t0 + 3;
    }
}

// ---------------- prep: gathered x->fp16 pack  +  W transpose->fp16 ----------------
// blocks [0, TQ):            g_xh[p][:] = half(x[g_perm[p]][:])
// blocks [TQ, TQ + 8*1024):  g_Wth[e][o][k] = half(W[e][k][o])
__global__ void k_prep(const float* __restrict__ x, const float* __restrict__ W) {
    const int tid = threadIdx.x;
    if (blockIdx.x < TQ) {
        int p = blockIdx.x;
        int tok = g_perm[p];
        float4 v = *reinterpret_cast<const float4*>(x + (size_t)tok * DIN + tid * 4);
        __half2 h0 = __float22half2_rn(make_float2(v.x, v.y));
        __half2 h1 = __float22half2_rn(make_float2(v.z, v.w));
        __half* dst = g_xh + (size_t)p * DIN + tid * 4;
        *reinterpret_cast<__half2*>(dst)     = h0;
        *reinterpret_cast<__half2*>(dst + 2) = h1;
    } else {
        __shared__ float t[32][33];
        int bid = blockIdx.x - TQ;
        int e = bid >> 10;
        int rem = bid & 1023;
        int k0 = (rem >> 5) * 32, o0 = (rem & 31) * 32;
        const float* Ws = W + (size_t)e * DIN * DOUT;
        __half* Wd = g_Wth + (size_t)e * DOUT * DIN;
        int tx = tid & 31, ty = tid >> 5;   // 32 x 8
#pragma unroll
        for (int j = 0; j < 4; j++)
            t[ty + j * 8][tx] = Ws[(size_t)(k0 + ty + j * 8) * DOUT + o0 + tx];
        __syncthreads();
#pragma unroll
        for (int j = 0; j < 4; j++)
            Wd[(size_t)(o0 + ty + j * 8) * DIN + k0 + tx] = __float2half(t[tx][ty + j * 8]);
    }
}

// ---------------- GEMM helpers ----------------
__device__ __forceinline__ void cp_async16(uint32_t dst, const void* src) {
    asm volatile("cp.async.cg.shared.global [%0], [%1], 16;\n" :: "r"(dst), "l"(src));
}

__device__ __forceinline__ void ldsm_x4(uint32_t r[4], uint32_t addr) {
    asm volatile("ldmatrix.sync.aligned.m8n8.x4.shared.b16 {%0,%1,%2,%3}, [%4];"
                 : "=r"(r[0]), "=r"(r[1]), "=r"(r[2]), "=r"(r[3]) : "r"(addr));
}

__device__ __forceinline__ void mma_f16(float d[4], const uint32_t a[4], const uint32_t b[2]) {
    asm volatile(
        "mma.sync.aligned.m16n8k16.row.col.f32.f16.f16.f32 "
        "{%0,%1,%2,%3}, {%4,%5,%6,%7}, {%8,%9}, {%0,%1,%2,%3};\n"
        : "+f"(d[0]), "+f"(d[1]), "+f"(d[2]), "+f"(d[3])
        : "r"(a[0]), "r"(a[1]), "r"(a[2]), "r"(a[3]),
          "r"(b[0]), "r"(b[1]));
}

__device__ __forceinline__ uint32_t smem_u32(const void* p) {
    return (uint32_t)__cvta_generic_to_shared(p);
}

// ---------------- GEMM (round-9 config: 8 warps of 64x32, 256 thr, 2 CTAs/SM) -------
// grid=(DOUT/BN, MAXTILES): n fastest so CTAs sharing a row-tile hit L2 on packed A rows.
__global__ __launch_bounds__(256, 2)
void k_gemm(const float* __restrict__ bias, float* __restrict__ y)
{
    const int tile = blockIdx.y;
    const int e = g_tile_expert[tile];
    if (e < 0) return;
    const int row0 = g_tile_start[tile];
    const int row_end = g_offsets[e + 1];
    const int n0 = blockIdx.x * BN;

    extern __shared__ __half smem[];
    const uint32_t sbase = smem_u32(smem);
    __shared__ float sbias[BN];

    const int tid  = threadIdx.x;
    const int lane = tid & 31;
    const int warp = tid >> 5;
    const int warpM = warp >> 2;     // 0..1  (64-row slab)
    const int warpN = warp & 3;      // 0..3  (32-col slab)

    if (tid < BN) sbias[tid] = bias[e * DOUT + n0 + tid];

    const int q  = lane >> 3;        // ldmatrix matrix id
    const int rl = lane & 7;         // row within 8x8 matrix

    // A: matrices [m0-7,k0-7][m8-15,k0-7][m0-7,k8-15][m8-15,k8-15]
    uint32_t aoff[4];
#pragma unroll
    for (int mi = 0; mi < 4; mi++) {
        int row = warpM * 64 + mi * 16 + (q & 1) * 8 + rl;
        aoff[mi] = (uint32_t)(row * TSTRIDE_H + (q >> 1) * 8) * 2;
    }
    // B (n-major rows of W^T): matrices [n0-7,k0-7][n0-7,k8-15][n8-15,k0-7][n8-15,k8-15]
    uint32_t boff[2];
#pragma unroll
    for (int j = 0; j < 2; j++) {
        int row = warpN * 32 + 16 * j + (q >> 1) * 8 + rl;
        boff[j] = (uint32_t)(row * TSTRIDE_H + (q & 1) * 8) * 2 + TILE_BYTES;
    }

    const __half* wt = g_Wth + (size_t)(e * DOUT + n0) * DIN;
    const int cc = tid & 7;           // 16B chunk col (8 halves each)

    int arow[4];
#pragma unroll
    for (int i = 0; i < 4; i++) {
        int r = (i * 256 + tid) >> 3;
        int gr = row0 + r;
        arow[i] = (gr < TQ) ? gr : (TQ - 1);
    }

    auto prefetch = [&](int kt) {
        const uint32_t st = sbase + (kt % NSTAGE) * STAGE_BYTES;
        const int k0 = kt * BK;
#pragma unroll
        for (int i = 0; i < 4; i++) {
            int r = (i * 256 + tid) >> 3;
            cp_async16(st + (uint32_t)(r * TSTRIDE_H + cc * 8) * 2,
                       g_xh + (size_t)arow[i] * DIN + k0 + cc * 8);
        }
#pragma unroll
        for (int i = 0; i < 4; i++) {
            int n = (i * 256 + tid) >> 3;
            cp_async16(st + TILE_BYTES + (uint32_t)(n * TSTRIDE_H + cc * 8) * 2,
                       wt + (size_t)n * DIN + k0 + cc * 8);
        }
        asm volatile("cp.async.commit_group;\n" ::);
    };

    float acc[4][4][4] = {};   // [mi][nj][frag]

    prefetch(0);
    prefetch(1);

    for (int kt = 0; kt < NKITER; kt++) {
        if (kt < NKITER - 1) {
            asm volatile("cp.async.wait_group 1;\n" ::);
        } else {
            asm volatile("cp.async.wait_group 0;\n" ::);
        }
        __syncthreads();
        if (kt + 2 < NKITER) prefetch(kt + 2);

        const uint32_t st = sbase + (kt % NSTAGE) * STAGE_BYTES;

#pragma unroll
        for (int ks = 0; ks < BK; ks += 16) {
            uint32_t af[4][4], bp[2][4];
#pragma unroll
            for (int mi = 0; mi < 4; mi++)
                ldsm_x4(af[mi], st + aoff[mi] + ks * 2);
#pragma unroll
            for (int j = 0; j < 2; j++)
                ldsm_x4(bp[j], st + boff[j] + ks * 2);
            // bp[j]: r0,r1 = B frag for n-octet 2j; r2,r3 = n-octet 2j+1
#pragma unroll
            for (int mi = 0; mi < 4; mi++)
#pragma unroll
                for (int nj = 0; nj < 4; nj++)
                    mma_f16(acc[mi][nj], af[mi], &bp[nj >> 1][(nj & 1) * 2]);
        }
    }

    // Epilogue: bias + relu + scatter store (perm only here)
    const int grp = lane >> 2;
    const int c4  = lane & 3;
#pragma unroll
    for (int mi = 0; mi < 4; mi++) {
#pragma unroll
        for (int h = 0; h < 2; h++) {
            int mrow = warpM * 64 + mi * 16 + grp + h * 8;
            int gr = row0 + mrow;
            if (gr >= row_end) continue;
            int tok = g_perm[gr];
#pragma unroll
            for (int nj = 0; nj < 4; nj++) {
                int nn = warpN * 32 + nj * 8 + 2 * c4;
                float v0 = acc[mi][nj][h * 2 + 0] + sbias[nn];
                float v1 = acc[mi][nj][h * 2 + 1] + sbias[nn + 1];
                float2 out;
                out.x = fmaxf(v0, 0.0f);
                out.y = fmaxf(v1, 0.0f);
                *reinterpret_cast<float2*>(y + (size_t)tok * DOUT + n0 + nn) = out;
            }
        }
    }
}

// ---------------- launch ----------------
extern "C" void kernel_launch(void* const* d_in, const int* in_sizes, int n_in,
                              void* d_out, int out_size) {
    const float* x    = (const float*)d_in[0];
    const int*   idxs = (const int*)  d_in[1];
    const float* W    = (const float*)d_in[2];
    const float* b    = (const float*)d_in[3];
    float* y = (float*)d_out;

    cudaFuncSetAttribute(k_gemm, cudaFuncAttributeMaxDynamicSharedMemorySize, SMEM_BYTES);

    k_binscatter<<<1, 1024>>>(idxs);
    k_prep<<<TQ + NE * (DIN / 32) * (DOUT / 32), 256>>>(x, W);

    dim3 grid(DOUT / BN, MAXTILES);
    k_gemm<<<grid, 256, SMEM_BYTES>>>(b, y);
}